// round 8
// baseline (speedup 1.0000x reference)
#include <cuda_runtime.h>
#include <cstdint>

// CBModel: output = concat(gen_poses [2,32,18,256,256], step_poses [2,32,18,256,256]) fp32
//   = 150,994,944 floats = 604 MB, all zeros except <=2304 one-hot elements.
//
// Established facts (R4-R7): aggregate write ceiling ~7.0-7.4 TB/s regardless of
// path mix (driver memset fastest at ~7.37 TB/s); concurrency cannot beat
// bytes/ceiling. Remaining target: the trailing ones-kernel latency (~4us).
//
// Structure:
//   s0: memset A (planes [0,2048), 512 MB)  ── evA ──>  memset B (planes [2048,2304), 64 MB)
//   s1:                       wait evA ──> ones-A kernel (2048 planes)   [hidden under memset B]
//   s0: ones-B kernel (256 planes, sector-complete 32B writes)           [only trailing work]
//   join s0 <- s1.

static constexpr int BC      = 32 * 18;    // 576
static constexpr int C_KP    = 18;
static constexpr int HW      = 256 * 256;  // 65536 floats per plane
static constexpr int PLANES  = 4 * BC;     // 2304

static constexpr int SPLIT   = 2048;               // planes in memset A
static constexpr int TAILP   = PLANES - SPLIT;     // 256 planes in memset B

// Hot index for a plane: -1 if out of bounds, else x*256+y.
// Bit-exact to the reference: jnp.trunc+int32 == C trunc cast; floor_divide via
// floorf((b-a)/3); step coords accumulated sequentially (two float roundings).
__device__ __forceinline__ int plane_hot(int plane,
                                         const float* __restrict__ pose1,
                                         const float* __restrict__ pose2)
{
    float cx, cy;
    if (plane < 2 * BC) {
        // gen half: sample-0 coords, replicated over batch
        const int k   = plane / BC;            // 0 -> pose1, 1 -> pose2
        const int rem = plane - k * BC;
        const int c   = rem % C_KP;
        const float* P = k ? pose2 : pose1;
        cx = P[2 * c];
        cy = P[2 * c + 1];
    } else {
        const int q   = plane - 2 * BC;
        const int s   = q / BC;                // 0 -> one step, 1 -> two steps
        const int rem = q - s * BC;            // rem = b*18 + c
        const float ax = pose1[2 * rem],  ay = pose1[2 * rem + 1];
        const float bx = pose2[2 * rem],  by = pose2[2 * rem + 1];
        const float sx = floorf((bx - ax) / 3.0f);
        const float sy = floorf((by - ay) / 3.0f);
        cx = ax + sx;  cy = ay + sy;
        if (s == 1) { cx += sx; cy += sy; }
    }
    const int x = (int)cx;
    const int y = (int)cy;
    const bool valid = (x >= 0) & (x <= 255) & (y >= 0) & (y <= 255);
    return valid ? ((x << 8) | y) : -1;
}

// Write the hot 1.0 as a full 32B sector (8 floats, two STG.128): the 7
// neighbors are zeros by construction (memset ran first; <=1 hot per plane),
// and full-sector stores avoid byte-masked partial DRAM writes.
__device__ __forceinline__ void write_hot_sector(float* __restrict__ out,
                                                 int plane, int hot)
{
    const int sec  = hot & ~7;                 // 32B-aligned (plane base is 256KB-aligned)
    const int lane = hot & 7;
    float4 lo = make_float4(0.f, 0.f, 0.f, 0.f);
    float4 hi = make_float4(0.f, 0.f, 0.f, 0.f);
    float* plo = (&lo.x) ;
    if (lane < 4) plo[lane] = 1.0f; else (&hi.x)[lane - 4] = 1.0f;
    float4* dst = reinterpret_cast<float4*>(out + (size_t)plane * HW + sec);
    dst[0] = lo;
    dst[1] = hi;
}

// ones-A: planes [0, SPLIT). 8 blocks x 256 threads.
__global__ __launch_bounds__(256)
void cbmodel_ones_a_kernel(const float* __restrict__ pose1,
                           const float* __restrict__ pose2,
                           float* __restrict__ out)
{
    const int plane = blockIdx.x * 256 + threadIdx.x;
    if (plane < SPLIT) {
        const int hot = plane_hot(plane, pose1, pose2);
        if (hot >= 0) write_hot_sector(out, plane, hot);
    }
}

// ones-B: planes [SPLIT, PLANES). 1 block x 256 threads (latency-critical tail).
__global__ __launch_bounds__(256)
void cbmodel_ones_b_kernel(const float* __restrict__ pose1,
                           const float* __restrict__ pose2,
                           float* __restrict__ out)
{
    const int plane = SPLIT + threadIdx.x;     // TAILP == 256 == blockDim
    const int hot = plane_hot(plane, pose1, pose2);
    if (hot >= 0) write_hot_sector(out, plane, hot);
}

extern "C" void kernel_launch(void* const* d_in, const int* in_sizes, int n_in,
                              void* d_out, int out_size)
{
    const float* pose1 = (const float*)d_in[0];   // [32,18,2] float32
    const float* pose2 = (const float*)d_in[1];   // [32,18,2] float32
    float* out = (float*)d_out;

    (void)in_sizes; (void)n_in; (void)out_size;

    // Host-side stream/event creation (no device memory; intentionally leaked;
    // kernel_launch is invoked only twice: correctness + capture).
    cudaStream_t s1;
    cudaStreamCreateWithFlags(&s1, cudaStreamNonBlocking);
    cudaEvent_t evA, evJoin;
    cudaEventCreateWithFlags(&evA, cudaEventDisableTiming);
    cudaEventCreateWithFlags(&evJoin, cudaEventDisableTiming);

    const size_t bytesA = (size_t)SPLIT * HW * sizeof(float);   // 512 MB
    const size_t bytesB = (size_t)TAILP * HW * sizeof(float);   //  64 MB

    // s0: memset A (head planes)
    cudaMemsetAsync(out, 0, bytesA, 0);
    cudaEventRecord(evA, 0);

    // s1: ones for head planes, concurrent with memset B
    cudaStreamWaitEvent(s1, evA, 0);
    cbmodel_ones_a_kernel<<<(SPLIT + 255) / 256, 256, 0, s1>>>(pose1, pose2, out);

    // s0: memset B (tail planes), then the only serialized trailing work: ones-B
    cudaMemsetAsync((char*)out + bytesA, 0, bytesB, 0);
    cbmodel_ones_b_kernel<<<1, 256>>>(pose1, pose2, out);

    // join
    cudaEventRecord(evJoin, s1);
    cudaStreamWaitEvent(0, evJoin, 0);
}